// round 17
// baseline (speedup 1.0000x reference)
#include <cuda_runtime.h>
#include <cuda_fp16.h>

// TrilinearInterpolation, single-launch, CTA-specialized (static partition).
// d_out = [lut passthrough (107811 f32)][out (32,3,512,512) f32].
//
// CTAs [0, n1)    : smem = half2(ch0[i], ch1[i])       8 LDS/px, ch0+ch1, U1=2
// CTAs [n1, grid) : smem = half2(c2[i], c2[i+1]-c2[i]) 4 LDS/px, ch2,     U2=4
// R16 state: at the 12-LDS/px wavefront floor (47.4us busy), 13.5% crossbar
// idle partly caused by issue pressure. This round: group01 x/y-lerp done in
// half2 (both channels per HFMA2; ~46 -> ~22 math ops/px), float-index base
// computation (exact integer FFMA). z-lerp stays fp32; group2 stays fp32.

constexpr int D   = 33;
constexpr int DD  = D * D;          // 1089
constexpr int D3  = D * D * D;      // 35937
constexpr int HW  = 512 * 512;      // 262144
constexpr int NPX = 32 * HW;        // 8388608
constexpr int SMEM_BYTES = D3 * 4;  // 143748
constexpr int BLK = 1024;

constexpr int U1 = 2;
constexpr int STEP1 = BLK * U1;         // 2048 (divides HW)
constexpr int NB1   = NPX / STEP1;      // 4096

constexpr int U2 = 4;
constexpr int STEP2 = BLK * U2;         // 4096 (divides HW)
constexpr int NB2   = NPX / STEP2;      // 2048

// Reference-equivalent clip/floor for r >= 0:
// x = clip(r*32,0,32); x0 = clip(floor(x),0,31); w = x-x0.
// base computed as exact integer FFMA (all values < 2^24).
__device__ __forceinline__ void coords(float r, float g, float b,
                                       int& base, float& wx, float& wy, float& wz)
{
    float x = __saturatef(r) * 32.0f;
    float y = __saturatef(g) * 32.0f;
    float z = __saturatef(b) * 32.0f;
    float xf = fminf(floorf(x), 31.0f);
    float yf = fminf(floorf(y), 31.0f);
    float zf = fminf(floorf(z), 31.0f);
    wx = x - xf;
    wy = y - yf;
    wz = z - zf;
    base = (int)fmaf(zf, 1089.0f, fmaf(yf, 33.0f, xf));
}

struct Px1 { float r[U1], g[U1], b[U1]; };
struct Px2 { float r[U2], g[U2], b[U2]; };

__device__ __forceinline__ Px1 load1(const float* __restrict__ img, int blk, int tid)
{
    Px1 p;
    const int px0 = blk * STEP1;
    const int ib  = ((px0 >> 18) * 3) << 18;
    const int hw0 = (px0 & (HW - 1)) + tid;
    #pragma unroll
    for (int k = 0; k < U1; ++k) {
        int hw = hw0 + k * BLK;
        p.r[k] = __ldg(img + ib + hw);
        p.g[k] = __ldg(img + ib + HW + hw);
        p.b[k] = __ldg(img + ib + 2 * HW + hw);
    }
    return p;
}

__device__ __forceinline__ Px2 load2(const float* __restrict__ img, int blk, int tid)
{
    Px2 p;
    const int px0 = blk * STEP2;
    const int ib  = ((px0 >> 18) * 3) << 18;
    const int hw0 = (px0 & (HW - 1)) + tid;
    #pragma unroll
    for (int k = 0; k < U2; ++k) {
        int hw = hw0 + k * BLK;
        p.r[k] = __ldg(img + ib + hw);
        p.g[k] = __ldg(img + ib + HW + hw);
        p.b[k] = __ldg(img + ib + 2 * HW + hw);
    }
    return p;
}

__device__ __forceinline__ void proc1(const __half2* __restrict__ st,
                                      float* __restrict__ out,
                                      int blk, int tid, const Px1& p)
{
    const int px0 = blk * STEP1;
    const int ib  = ((px0 >> 18) * 3) << 18;
    const int hw0 = (px0 & (HW - 1)) + tid;

    // Phase A: all coords.
    int base[U1]; float wx[U1], wy[U1], wz[U1];
    #pragma unroll
    for (int k = 0; k < U1; ++k)
        coords(p.r[k], p.g[k], p.b[k], base[k], wx[k], wy[k], wz[k]);

    // Phase B: all 16 LDS issued back-to-back (max smem-MLP).
    __half2 q[U1][8];
    #pragma unroll
    for (int k = 0; k < U1; ++k) {
        int bse = base[k];
        q[k][0] = st[bse];          q[k][1] = st[bse + 1];
        q[k][2] = st[bse + D];      q[k][3] = st[bse + D + 1];
        q[k][4] = st[bse + DD];     q[k][5] = st[bse + DD + 1];
        q[k][6] = st[bse + DD + D]; q[k][7] = st[bse + DD + D + 1];
    }

    // Phase C: x/y lerp in half2 (both channels per op), z lerp in fp32.
    #pragma unroll
    for (int k = 0; k < U1; ++k) {
        __half2 wx2 = __float2half2_rn(wx[k]);
        __half2 wy2 = __float2half2_rn(wy[k]);

        __half2 a00 = __hfma2(wx2, __hsub2(q[k][1], q[k][0]), q[k][0]);
        __half2 a01 = __hfma2(wx2, __hsub2(q[k][3], q[k][2]), q[k][2]);
        __half2 a10 = __hfma2(wx2, __hsub2(q[k][5], q[k][4]), q[k][4]);
        __half2 a11 = __hfma2(wx2, __hsub2(q[k][7], q[k][6]), q[k][6]);
        __half2 b0h = __hfma2(wy2, __hsub2(a01, a00), a00);
        __half2 b1h = __hfma2(wy2, __hsub2(a11, a10), a10);

        float2 f0 = __half22float2(b0h);
        float2 f1 = __half22float2(b1h);
        float r0 = fmaf(wz[k], f1.x - f0.x, f0.x);
        float r1 = fmaf(wz[k], f1.y - f0.y, f0.y);

        int hw = hw0 + k * BLK;
        __stcs(out + ib + hw, r0);             // c=0 plane
        __stcs(out + ib + HW + hw, r1);        // c=1 plane
    }
}

__device__ __forceinline__ void proc2(const __half2* __restrict__ st,
                                      float* __restrict__ out,
                                      int blk, int tid, const Px2& p)
{
    const int px0 = blk * STEP2;
    const int ib  = ((px0 >> 18) * 3) << 18;
    const int hw0 = (px0 & (HW - 1)) + tid;

    // Phase A: all coords.
    int base[U2]; float wx[U2], wy[U2], wz[U2];
    #pragma unroll
    for (int k = 0; k < U2; ++k)
        coords(p.r[k], p.g[k], p.b[k], base[k], wx[k], wy[k], wz[k]);

    // Phase B: all 16 LDS issued back-to-back.
    __half2 q[U2][4];
    #pragma unroll
    for (int k = 0; k < U2; ++k) {
        int bse = base[k];
        q[k][0] = st[bse];          // (v, v_next - v)
        q[k][1] = st[bse + D];
        q[k][2] = st[bse + DD];
        q[k][3] = st[bse + DD + D];
    }

    // Phase C: math + stores (fp32; lanes are (v, delta), not channels).
    #pragma unroll
    for (int k = 0; k < U2; ++k) {
        float2 e00 = __half22float2(q[k][0]);
        float2 e01 = __half22float2(q[k][1]);
        float2 e10 = __half22float2(q[k][2]);
        float2 e11 = __half22float2(q[k][3]);

        float a00 = fmaf(wx[k], e00.y, e00.x);
        float a01 = fmaf(wx[k], e01.y, e01.x);
        float a10 = fmaf(wx[k], e10.y, e10.x);
        float a11 = fmaf(wx[k], e11.y, e11.x);
        float b0  = fmaf(wy[k], a01 - a00, a00);
        float b1  = fmaf(wy[k], a11 - a10, a10);

        __stcs(out + ib + 2 * HW + hw0 + k * BLK,
               fmaf(wz[k], b1 - b0, b0));      // c=2 plane
    }
}

__global__ __launch_bounds__(BLK, 1)
void trilerp_kernel(const float* __restrict__ lut,
                    const float* __restrict__ img,
                    float* __restrict__ out_full)   // = d_out (tuple base)
{
    extern __shared__ unsigned int sm[];
    const int tid = threadIdx.x;
    const int n1  = ((int)gridDim.x * 129) / 200;   // 98 of 152
    const bool is01 = (int)blockIdx.x < n1;
    float* out = out_full + 3 * D3;                 // trilerp output region

    // LUT passthrough (grid-strided; ~0.7 elements/thread).
    for (int j = blockIdx.x * BLK + tid; j < 3 * D3; j += (int)gridDim.x * BLK)
        out_full[j] = __ldg(lut + j);

    // Stage + convert this group's table (unrolled so L2 latency pipelines).
    if (is01) {
        #pragma unroll 8
        for (int i = tid; i < D3; i += BLK) {
            __half2 h = __floats2half2_rn(__ldg(lut + i), __ldg(lut + D3 + i));
            sm[i] = *reinterpret_cast<unsigned int*>(&h);
        }
    } else {
        #pragma unroll 8
        for (int i = tid; i < D3; i += BLK) {
            float v  = __ldg(lut + 2 * D3 + i);
            float vn = (i + 1 < D3) ? __ldg(lut + 2 * D3 + i + 1) : v;
            __half2 h = __floats2half2_rn(v, vn - v);
            sm[i] = *reinterpret_cast<unsigned int*>(&h);
        }
    }

    if (is01) {
        int blk = blockIdx.x;
        if (blk < NB1) {
            Px1 cur = load1(img, blk, tid);   // prefetch BEFORE barrier
            __syncthreads();
            const __half2* st = reinterpret_cast<const __half2*>(sm);
            int nxt = blk + n1;
            while (nxt < NB1) {
                Px1 pre = load1(img, nxt, tid);   // prefetch next block
                proc1(st, out, blk, tid, cur);    // process current
                cur = pre;
                blk = nxt;
                nxt += n1;
            }
            proc1(st, out, blk, tid, cur);
        } else {
            __syncthreads();
        }
    } else {
        const int n2 = (int)gridDim.x - n1;
        int blk = blockIdx.x - n1;
        if (blk < NB2) {
            Px2 cur = load2(img, blk, tid);   // prefetch BEFORE barrier
            __syncthreads();
            const __half2* st = reinterpret_cast<const __half2*>(sm);
            int nxt = blk + n2;
            while (nxt < NB2) {
                Px2 pre = load2(img, nxt, tid);
                proc2(st, out, blk, tid, cur);
                cur = pre;
                blk = nxt;
                nxt += n2;
            }
            proc2(st, out, blk, tid, cur);
        } else {
            __syncthreads();
        }
    }
}

extern "C" void kernel_launch(void* const* d_in, const int* in_sizes, int n_in,
                              void* d_out, int out_size)
{
    const float* lut = (const float*)d_in[0];
    const float* img = (const float*)d_in[1];
    if (n_in >= 2 && in_sizes[0] > in_sizes[1]) {   // defensive input-order check
        lut = (const float*)d_in[1];
        img = (const float*)d_in[0];
    }
    float* out = (float*)d_out;

    cudaFuncSetAttribute(trilerp_kernel,
                         cudaFuncAttributeMaxDynamicSharedMemorySize, SMEM_BYTES);

    int sms = 148;
    cudaDeviceGetAttribute(&sms, cudaDevAttrMultiProcessorCount, 0);

    trilerp_kernel<<<sms, BLK, SMEM_BYTES>>>(lut, img, out);
}